// round 1
// baseline (speedup 1.0000x reference)
#include <cuda_runtime.h>

#define N_NODES 100000
#define N_EDGES 800000
#define D 128
#define NCLS 64

// ---------------- scratch (static device globals; no allocation) ------------
__device__ float g_m  [(size_t)N_NODES * D];
__device__ float g_agg[(size_t)N_NODES * D];
__device__ float g_h1 [(size_t)N_NODES * D];
__device__ float g_h2 [(size_t)N_NODES * D];
__device__ int   g_row_start[N_NODES + 1];
__device__ int   g_next[N_NODES];
__device__ int   g_csr [N_EDGES];

// ---------------- CSR build -------------------------------------------------
__global__ void zero_counts_kernel() {
    int i = blockIdx.x * blockDim.x + threadIdx.x;
    if (i < N_NODES) g_next[i] = 0;
}

__global__ void hist_kernel(const int* __restrict__ dst) {
    int e = blockIdx.x * blockDim.x + threadIdx.x;
    if (e < N_EDGES) atomicAdd(&g_next[dst[e]], 1);
}

// single-block exclusive scan of g_next (counts) -> g_row_start, g_next (fill cursors)
__global__ void scan_kernel() {
    __shared__ int buf[1024];
    __shared__ int carry;
    int tid = threadIdx.x;
    if (tid == 0) carry = 0;
    __syncthreads();
    for (int base = 0; base < N_NODES; base += 1024) {
        int i = base + tid;
        int v = (i < N_NODES) ? g_next[i] : 0;
        buf[tid] = v;
        __syncthreads();
        #pragma unroll
        for (int off = 1; off < 1024; off <<= 1) {
            int t = (tid >= off) ? buf[tid - off] : 0;
            __syncthreads();
            buf[tid] += t;
            __syncthreads();
        }
        int incl  = buf[tid];
        int total = buf[1023];
        int excl  = incl - v + carry;
        if (i < N_NODES) { g_row_start[i] = excl; g_next[i] = excl; }
        __syncthreads();
        if (tid == 0) carry += total;
        __syncthreads();
    }
    if (tid == 0) g_row_start[N_NODES] = carry;
}

__global__ void fill_kernel(const int* __restrict__ src, const int* __restrict__ dst) {
    int e = blockIdx.x * blockDim.x + threadIdx.x;
    if (e < N_EDGES) {
        int pos = atomicAdd(&g_next[dst[e]], 1);
        g_csr[pos] = src[e];
    }
}

// ---------------- segment-max aggregation (warp per node) -------------------
// relu output is >= 0, so acc init 0 == segment_max with -inf->0 fixup.
__global__ void agg_kernel() {
    int warp = (blockIdx.x * blockDim.x + threadIdx.x) >> 5;
    int lane = threadIdx.x & 31;
    if (warp >= N_NODES) return;
    int s = g_row_start[warp];
    int e = g_row_start[warp + 1];
    float4 acc = make_float4(0.f, 0.f, 0.f, 0.f);
    const float* mp = g_m;
    int i = s;
    for (; i + 2 <= e; i += 2) {
        int s0 = g_csr[i], s1 = g_csr[i + 1];
        float4 v0 = *(const float4*)(mp + (size_t)s0 * D + lane * 4);
        float4 v1 = *(const float4*)(mp + (size_t)s1 * D + lane * 4);
        acc.x = fmaxf(acc.x, fmaxf(v0.x, v1.x));
        acc.y = fmaxf(acc.y, fmaxf(v0.y, v1.y));
        acc.z = fmaxf(acc.z, fmaxf(v0.z, v1.z));
        acc.w = fmaxf(acc.w, fmaxf(v0.w, v1.w));
    }
    if (i < e) {
        int s0 = g_csr[i];
        float4 v0 = *(const float4*)(mp + (size_t)s0 * D + lane * 4);
        acc.x = fmaxf(acc.x, v0.x);
        acc.y = fmaxf(acc.y, v0.y);
        acc.z = fmaxf(acc.z, v0.z);
        acc.w = fmaxf(acc.w, v0.w);
    }
    *(float4*)(g_agg + (size_t)warp * D + lane * 4) = acc;
}

// ---------------- tiled fp32 GEMM: C = relu(A1@B1 (+ A2@B2) + bias) ---------
// A: [M,128] row-major, B: [128,BN] row-major, C: [M,BN]
template<int BN, int TN, bool DUAL>
__global__ void __launch_bounds__(256, 2)
gemm_relu_kernel(const float* __restrict__ A1, const float* __restrict__ B1,
                 const float* __restrict__ A2, const float* __restrict__ B2,
                 const float* __restrict__ bias, float* __restrict__ C, int M)
{
    constexpr int BM = 128, BK = 16, TM = 8;
    __shared__ float As[BK][BM + 4];
    __shared__ float Bs[BK][BN];

    int tid = threadIdx.x;
    int tx = tid & 15;        // 0..15 -> col group
    int ty = tid >> 4;        // 0..15 -> row group
    int rowBase = blockIdx.x * BM;

    float acc[TM][TN];
    #pragma unroll
    for (int i = 0; i < TM; i++)
        #pragma unroll
        for (int j = 0; j < TN; j++) acc[i][j] = 0.f;

    #pragma unroll 1
    for (int pass = 0; pass < (DUAL ? 2 : 1); pass++) {
        const float* A = (pass == 0) ? A1 : A2;
        const float* B = (pass == 0) ? B1 : B2;
        #pragma unroll 1
        for (int k0 = 0; k0 < D; k0 += BK) {
            // A tile: 128 rows x 16 cols, stored transposed As[k][m]
            #pragma unroll
            for (int q = 0; q < 2; q++) {
                int s  = tid * 2 + q;      // 0..511 float4 slots
                int r  = s >> 2;           // row in tile
                int kq = (s & 3) * 4;      // k sub-offset
                float4 v = make_float4(0.f, 0.f, 0.f, 0.f);
                int gr = rowBase + r;
                if (gr < M) v = *(const float4*)(A + (size_t)gr * D + k0 + kq);
                As[kq + 0][r] = v.x;
                As[kq + 1][r] = v.y;
                As[kq + 2][r] = v.z;
                As[kq + 3][r] = v.w;
            }
            // B tile: 16 rows x BN cols
            #pragma unroll
            for (int s = tid; s < 4 * BN; s += 256) {
                int r = s / (BN / 4);
                int c = (s % (BN / 4)) * 4;
                *(float4*)&Bs[r][c] = *(const float4*)(B + (size_t)(k0 + r) * BN + c);
            }
            __syncthreads();
            #pragma unroll
            for (int k = 0; k < BK; k++) {
                float4 a0 = *(const float4*)&As[k][ty * TM];
                float4 a1 = *(const float4*)&As[k][ty * TM + 4];
                float a[TM] = {a0.x, a0.y, a0.z, a0.w, a1.x, a1.y, a1.z, a1.w};
                float b[TN];
                #pragma unroll
                for (int j = 0; j < TN; j += 4) {
                    float4 bv = *(const float4*)&Bs[k][tx * TN + j];
                    b[j] = bv.x; b[j + 1] = bv.y; b[j + 2] = bv.z; b[j + 3] = bv.w;
                }
                #pragma unroll
                for (int i = 0; i < TM; i++)
                    #pragma unroll
                    for (int j = 0; j < TN; j++)
                        acc[i][j] += a[i] * b[j];
            }
            __syncthreads();
        }
    }

    float bv[TN];
    #pragma unroll
    for (int j = 0; j < TN; j++) bv[j] = bias[tx * TN + j];
    #pragma unroll
    for (int i = 0; i < TM; i++) {
        int gr = rowBase + ty * TM + i;
        if (gr < M) {
            #pragma unroll
            for (int j = 0; j < TN; j += 4) {
                float4 o;
                o.x = fmaxf(acc[i][j + 0] + bv[j + 0], 0.f);
                o.y = fmaxf(acc[i][j + 1] + bv[j + 1], 0.f);
                o.z = fmaxf(acc[i][j + 2] + bv[j + 2], 0.f);
                o.w = fmaxf(acc[i][j + 3] + bv[j + 3], 0.f);
                *(float4*)(C + (size_t)gr * BN + tx * TN + j) = o;
            }
        }
    }
}

// ---------------- log-softmax over 64 classes (warp per row, in-place) ------
__global__ void lsm_kernel(float* __restrict__ out, int M) {
    int warp = (blockIdx.x * blockDim.x + threadIdx.x) >> 5;
    int lane = threadIdx.x & 31;
    if (warp >= M) return;
    float2 v = *(float2*)(out + (size_t)warp * NCLS + lane * 2);
    float mx = fmaxf(v.x, v.y);
    #pragma unroll
    for (int o = 16; o; o >>= 1) mx = fmaxf(mx, __shfl_xor_sync(0xffffffffu, mx, o));
    float s = expf(v.x - mx) + expf(v.y - mx);
    #pragma unroll
    for (int o = 16; o; o >>= 1) s += __shfl_xor_sync(0xffffffffu, s, o);
    float l = mx + logf(s);
    v.x -= l; v.y -= l;
    *(float2*)(out + (size_t)warp * NCLS + lane * 2) = v;
}

// ---------------- launch ----------------------------------------------------
extern "C" void kernel_launch(void* const* d_in, const int* in_sizes, int n_in,
                              void* d_out, int out_size) {
    const float* x    = (const float*)d_in[0];
    const int*   esrc = (const int*)d_in[1];
    const int*   edst = (const int*)d_in[2];
    const float *Wp[3], *bp[3], *Ws[3], *Wn[3], *bn[3];
    for (int l = 0; l < 3; l++) {
        Wp[l] = (const float*)d_in[3 + 5 * l + 0];
        bp[l] = (const float*)d_in[3 + 5 * l + 1];
        Ws[l] = (const float*)d_in[3 + 5 * l + 2];
        Wn[l] = (const float*)d_in[3 + 5 * l + 3];
        bn[l] = (const float*)d_in[3 + 5 * l + 4];
    }
    const int M = N_NODES;

    float *p_h1, *p_h2, *p_m, *p_agg;
    cudaGetSymbolAddress((void**)&p_h1,  g_h1);
    cudaGetSymbolAddress((void**)&p_h2,  g_h2);
    cudaGetSymbolAddress((void**)&p_m,   g_m);
    cudaGetSymbolAddress((void**)&p_agg, g_agg);

    // CSR build (order-independent max => deterministic output)
    zero_counts_kernel<<<(N_NODES + 255) / 256, 256>>>();
    hist_kernel<<<(N_EDGES + 255) / 256, 256>>>(edst);
    scan_kernel<<<1, 1024>>>();
    fill_kernel<<<(N_EDGES + 255) / 256, 256>>>(esrc, edst);

    const int gemm_grid = (M + 127) / 128;
    const int agg_grid  = (N_NODES + 7) / 8;   // 8 warps/block

    const float* hin = x;
    // layer 0
    gemm_relu_kernel<128, 8, false><<<gemm_grid, 256>>>(hin, Wp[0], nullptr, nullptr, bp[0], p_m, M);
    agg_kernel<<<agg_grid, 256>>>();
    gemm_relu_kernel<128, 8, true><<<gemm_grid, 256>>>(hin, Ws[0], p_agg, Wn[0], bn[0], p_h1, M);
    // layer 1
    hin = p_h1;
    gemm_relu_kernel<128, 8, false><<<gemm_grid, 256>>>(hin, Wp[1], nullptr, nullptr, bp[1], p_m, M);
    agg_kernel<<<agg_grid, 256>>>();
    gemm_relu_kernel<128, 8, true><<<gemm_grid, 256>>>(hin, Ws[1], p_agg, Wn[1], bn[1], p_h2, M);
    // layer 2 (output 64 classes straight into d_out)
    hin = p_h2;
    gemm_relu_kernel<128, 8, false><<<gemm_grid, 256>>>(hin, Wp[2], nullptr, nullptr, bp[2], p_m, M);
    agg_kernel<<<agg_grid, 256>>>();
    gemm_relu_kernel<64, 4, true><<<gemm_grid, 256>>>(hin, Ws[2], p_agg, Wn[2], bn[2], (float*)d_out, M);

    lsm_kernel<<<(M + 7) / 8, 256>>>((float*)d_out, M);
}

// round 2
// speedup vs baseline: 2.0880x; 2.0880x over previous
#include <cuda_runtime.h>
#include <cstdint>

#define N_NODES 100000
#define N_EDGES 800000
#define D 128
#define NCLS 64

// ---------------- scratch (static device globals; no allocation) ------------
__device__ float g_m  [(size_t)N_NODES * D];
__device__ float g_agg[(size_t)N_NODES * D];
__device__ float g_h1 [(size_t)N_NODES * D];
__device__ float g_h2 [(size_t)N_NODES * D];
__device__ int   g_row_start[N_NODES + 1];
__device__ int   g_next[N_NODES];
__device__ int   g_csr [N_EDGES];

// ---------------- small helpers ---------------------------------------------
__device__ __forceinline__ uint32_t f2tf32(float f) {
    uint32_t r;
    asm volatile("cvt.rna.tf32.f32 %0, %1;" : "=r"(r) : "f"(f));
    return r;
}

__device__ __forceinline__ void cp_async16(void* smem, const void* gmem, bool pred) {
    uint32_t s = (uint32_t)__cvta_generic_to_shared(smem);
    int sz = pred ? 16 : 0;
    asm volatile("cp.async.cg.shared.global [%0], [%1], 16, %2;\n" :: "r"(s), "l"(gmem), "r"(sz));
}

__device__ __forceinline__ void mma_tf32(float c[4], const uint32_t a[4], const uint32_t b[2]) {
    asm volatile(
        "mma.sync.aligned.m16n8k8.row.col.f32.tf32.tf32.f32 "
        "{%0,%1,%2,%3}, {%4,%5,%6,%7}, {%8,%9}, {%0,%1,%2,%3};"
        : "+f"(c[0]), "+f"(c[1]), "+f"(c[2]), "+f"(c[3])
        : "r"(a[0]), "r"(a[1]), "r"(a[2]), "r"(a[3]), "r"(b[0]), "r"(b[1]));
}

// ---------------- CSR build -------------------------------------------------
__global__ void zero_counts_kernel() {
    int i = blockIdx.x * blockDim.x + threadIdx.x;
    if (i < N_NODES) g_next[i] = 0;
}

__global__ void hist_kernel(const int* __restrict__ dst) {
    int e = blockIdx.x * blockDim.x + threadIdx.x;
    if (e < N_EDGES) atomicAdd(&g_next[dst[e]], 1);
}

// shuffle-based single-block exclusive scan: counts (g_next) -> offsets
__global__ void scan_kernel() {
    __shared__ int wsums[32];
    __shared__ int s_carry;
    int tid = threadIdx.x, lane = tid & 31, wid = tid >> 5;
    if (tid == 0) s_carry = 0;
    __syncthreads();
    for (int base = 0; base < N_NODES; base += 4096) {
        int i0 = base + tid * 4;
        int v[4];
        #pragma unroll
        for (int j = 0; j < 4; j++) v[j] = (i0 + j < N_NODES) ? g_next[i0 + j] : 0;
        int tsum = v[0] + v[1] + v[2] + v[3];
        int incl = tsum;
        #pragma unroll
        for (int off = 1; off < 32; off <<= 1) {
            int n = __shfl_up_sync(0xffffffffu, incl, off);
            if (lane >= off) incl += n;
        }
        if (lane == 31) wsums[wid] = incl;
        __syncthreads();
        if (wid == 0) {
            int w = wsums[lane];
            int wincl = w;
            #pragma unroll
            for (int off = 1; off < 32; off <<= 1) {
                int n = __shfl_up_sync(0xffffffffu, wincl, off);
                if (lane >= off) wincl += n;
            }
            wsums[lane] = wincl - w;   // exclusive warp prefix
        }
        __syncthreads();
        int e = s_carry + wsums[wid] + (incl - tsum);
        #pragma unroll
        for (int j = 0; j < 4; j++) {
            if (i0 + j < N_NODES) { g_row_start[i0 + j] = e; g_next[i0 + j] = e; }
            e += v[j];
        }
        __syncthreads();
        if (tid == 1023) s_carry += wsums[31] + incl;
        __syncthreads();
    }
    if (threadIdx.x == 0) g_row_start[N_NODES] = s_carry;
}

__global__ void fill_kernel(const int* __restrict__ src, const int* __restrict__ dst) {
    int e = blockIdx.x * blockDim.x + threadIdx.x;
    if (e < N_EDGES) {
        int pos = atomicAdd(&g_next[dst[e]], 1);
        g_csr[pos] = src[e];
    }
}

// ---------------- segment-max aggregation (warp per node) -------------------
// relu output is >= 0, so acc init 0 == segment_max with -inf->0 fixup.
__global__ void agg_kernel() {
    int warp = (blockIdx.x * blockDim.x + threadIdx.x) >> 5;
    int lane = threadIdx.x & 31;
    if (warp >= N_NODES) return;
    int s = g_row_start[warp];
    int e = g_row_start[warp + 1];
    float4 acc = make_float4(0.f, 0.f, 0.f, 0.f);
    const float* mp = g_m;
    int i = s;
    for (; i + 4 <= e; i += 4) {
        int s0 = g_csr[i], s1 = g_csr[i + 1], s2 = g_csr[i + 2], s3 = g_csr[i + 3];
        float4 v0 = *(const float4*)(mp + (size_t)s0 * D + lane * 4);
        float4 v1 = *(const float4*)(mp + (size_t)s1 * D + lane * 4);
        float4 v2 = *(const float4*)(mp + (size_t)s2 * D + lane * 4);
        float4 v3 = *(const float4*)(mp + (size_t)s3 * D + lane * 4);
        acc.x = fmaxf(acc.x, fmaxf(fmaxf(v0.x, v1.x), fmaxf(v2.x, v3.x)));
        acc.y = fmaxf(acc.y, fmaxf(fmaxf(v0.y, v1.y), fmaxf(v2.y, v3.y)));
        acc.z = fmaxf(acc.z, fmaxf(fmaxf(v0.z, v1.z), fmaxf(v2.z, v3.z)));
        acc.w = fmaxf(acc.w, fmaxf(fmaxf(v0.w, v1.w), fmaxf(v2.w, v3.w)));
    }
    for (; i < e; i++) {
        int s0 = g_csr[i];
        float4 v0 = *(const float4*)(mp + (size_t)s0 * D + lane * 4);
        acc.x = fmaxf(acc.x, v0.x);
        acc.y = fmaxf(acc.y, v0.y);
        acc.z = fmaxf(acc.z, v0.z);
        acc.w = fmaxf(acc.w, v0.w);
    }
    *(float4*)(g_agg + (size_t)warp * D + lane * 4) = acc;
}

// ---------------- tf32 tensor-core GEMM -------------------------------------
// C[M,BN] = relu(A1@B1 (+ A2@B2) + bias); A row-major [M,128], B row-major [128,BN]
// Block: 256 threads, tile 128 x BN, BK=16, double-buffered cp.async.
template<int BN, bool DUAL>
__global__ void __launch_bounds__(256)
gemm_tc_kernel(const float* __restrict__ A1, const float* __restrict__ B1,
               const float* __restrict__ A2, const float* __restrict__ B2,
               const float* __restrict__ bias, float* __restrict__ C, int M)
{
    constexpr int AS = 20;          // A smem row stride (words)
    constexpr int BS = BN + 8;      // B smem row stride (words), == 8 mod 32
    constexpr int MT = (BN == 128) ? 2 : 1;   // m16 tiles per warp
    constexpr int WM = MT * 16;               // warp M extent
    __shared__ float As[2][128 * AS];
    __shared__ float Bs[2][16 * BS];

    const int tid = threadIdx.x;
    const int wid = tid >> 5;
    const int lane = tid & 31;
    const int g  = lane >> 2;       // groupID
    const int tg = lane & 3;        // threadID in group
    const int warpM = (BN == 128) ? (wid & 3) : wid;
    const int warpN = (BN == 128) ? (wid >> 2) : 0;
    const int rowBase = blockIdx.x * 128;

    float acc[MT][8][4];
    #pragma unroll
    for (int mt = 0; mt < MT; mt++)
        #pragma unroll
        for (int nt = 0; nt < 8; nt++)
            #pragma unroll
            for (int q = 0; q < 4; q++) acc[mt][nt][q] = 0.f;

    const int totalStages = (DUAL ? 2 : 1) * 8;   // 8 stages of BK=16 per pass

    auto load_stage = [&](int buf, int s) {
        int pass = s >> 3;
        int kk = (s & 7) * 16;
        const float* A = (DUAL && pass) ? A2 : A1;
        const float* B = (DUAL && pass) ? B2 : B1;
        // A tile: 128 x 16
        #pragma unroll
        for (int idx = tid; idx < 512; idx += 256) {
            int r = idx >> 2, c4 = (idx & 3) * 4;
            bool p = (rowBase + r) < M;
            cp_async16(&As[buf][r * AS + c4],
                       A + (size_t)(rowBase + r) * 128 + kk + c4, p);
        }
        // B tile: 16 x BN
        #pragma unroll
        for (int idx = tid; idx < 4 * BN; idx += 256) {
            int r = idx / (BN / 4), c4 = (idx % (BN / 4)) * 4;
            cp_async16(&Bs[buf][r * BS + c4],
                       B + (size_t)(kk + r) * BN + c4, true);
        }
        asm volatile("cp.async.commit_group;\n" ::);
    };

    load_stage(0, 0);

    for (int s = 0; s < totalStages; s++) {
        int buf = s & 1;
        if (s + 1 < totalStages) {
            load_stage(buf ^ 1, s + 1);
            asm volatile("cp.async.wait_group 1;\n" ::);
        } else {
            asm volatile("cp.async.wait_group 0;\n" ::);
        }
        __syncthreads();

        #pragma unroll
        for (int ks = 0; ks < 2; ks++) {
            uint32_t af[MT][4];
            #pragma unroll
            for (int mt = 0; mt < MT; mt++) {
                int r0 = warpM * WM + mt * 16 + g;
                const float* ap = As[buf];
                af[mt][0] = f2tf32(ap[(r0    ) * AS + ks * 8 + tg    ]);
                af[mt][1] = f2tf32(ap[(r0 + 8) * AS + ks * 8 + tg    ]);
                af[mt][2] = f2tf32(ap[(r0    ) * AS + ks * 8 + tg + 4]);
                af[mt][3] = f2tf32(ap[(r0 + 8) * AS + ks * 8 + tg + 4]);
            }
            uint32_t bf[8][2];
            #pragma unroll
            for (int nt = 0; nt < 8; nt++) {
                int c0 = warpN * 64 + nt * 8 + g;
                const float* bp = Bs[buf];
                bf[nt][0] = f2tf32(bp[(ks * 8 + tg    ) * BS + c0]);
                bf[nt][1] = f2tf32(bp[(ks * 8 + tg + 4) * BS + c0]);
            }
            #pragma unroll
            for (int mt = 0; mt < MT; mt++)
                #pragma unroll
                for (int nt = 0; nt < 8; nt++)
                    mma_tf32(acc[mt][nt], af[mt], bf[nt]);
        }
        __syncthreads();
    }

    // epilogue: bias + relu + store
    #pragma unroll
    for (int mt = 0; mt < MT; mt++) {
        int r0 = rowBase + warpM * WM + mt * 16 + g;
        #pragma unroll
        for (int nt = 0; nt < 8; nt++) {
            int c0 = warpN * 64 + nt * 8 + tg * 2;
            float bv0 = __ldg(bias + c0);
            float bv1 = __ldg(bias + c0 + 1);
            if (r0 < M) {
                float2 o;
                o.x = fmaxf(acc[mt][nt][0] + bv0, 0.f);
                o.y = fmaxf(acc[mt][nt][1] + bv1, 0.f);
                *(float2*)(C + (size_t)r0 * BN + c0) = o;
            }
            if (r0 + 8 < M) {
                float2 o;
                o.x = fmaxf(acc[mt][nt][2] + bv0, 0.f);
                o.y = fmaxf(acc[mt][nt][3] + bv1, 0.f);
                *(float2*)(C + (size_t)(r0 + 8) * BN + c0) = o;
            }
        }
    }
}

// ---------------- log-softmax over 64 classes (warp per row, in-place) ------
__global__ void lsm_kernel(float* __restrict__ out, int M) {
    int warp = (blockIdx.x * blockDim.x + threadIdx.x) >> 5;
    int lane = threadIdx.x & 31;
    if (warp >= M) return;
    float2 v = *(float2*)(out + (size_t)warp * NCLS + lane * 2);
    float mx = fmaxf(v.x, v.y);
    #pragma unroll
    for (int o = 16; o; o >>= 1) mx = fmaxf(mx, __shfl_xor_sync(0xffffffffu, mx, o));
    float s = expf(v.x - mx) + expf(v.y - mx);
    #pragma unroll
    for (int o = 16; o; o >>= 1) s += __shfl_xor_sync(0xffffffffu, s, o);
    float l = mx + logf(s);
    v.x -= l; v.y -= l;
    *(float2*)(out + (size_t)warp * NCLS + lane * 2) = v;
}

// ---------------- launch ----------------------------------------------------
extern "C" void kernel_launch(void* const* d_in, const int* in_sizes, int n_in,
                              void* d_out, int out_size) {
    const float* x    = (const float*)d_in[0];
    const int*   esrc = (const int*)d_in[1];
    const int*   edst = (const int*)d_in[2];
    const float *Wp[3], *bp[3], *Ws[3], *Wn[3], *bn[3];
    for (int l = 0; l < 3; l++) {
        Wp[l] = (const float*)d_in[3 + 5 * l + 0];
        bp[l] = (const float*)d_in[3 + 5 * l + 1];
        Ws[l] = (const float*)d_in[3 + 5 * l + 2];
        Wn[l] = (const float*)d_in[3 + 5 * l + 3];
        bn[l] = (const float*)d_in[3 + 5 * l + 4];
    }
    const int M = N_NODES;

    float *p_h1, *p_h2, *p_m, *p_agg;
    cudaGetSymbolAddress((void**)&p_h1,  g_h1);
    cudaGetSymbolAddress((void**)&p_h2,  g_h2);
    cudaGetSymbolAddress((void**)&p_m,   g_m);
    cudaGetSymbolAddress((void**)&p_agg, g_agg);

    // CSR build (order-independent max => deterministic output)
    zero_counts_kernel<<<(N_NODES + 255) / 256, 256>>>();
    hist_kernel<<<(N_EDGES + 255) / 256, 256>>>(edst);
    scan_kernel<<<1, 1024>>>();
    fill_kernel<<<(N_EDGES + 255) / 256, 256>>>(esrc, edst);

    const int gemm_grid = (M + 127) / 128;
    const int agg_grid  = (N_NODES + 7) / 8;   // 8 warps/block

    const float* hin = x;
    // layer 0
    gemm_tc_kernel<128, false><<<gemm_grid, 256>>>(hin, Wp[0], nullptr, nullptr, bp[0], p_m, M);
    agg_kernel<<<agg_grid, 256>>>();
    gemm_tc_kernel<128, true><<<gemm_grid, 256>>>(hin, Ws[0], p_agg, Wn[0], bn[0], p_h1, M);
    // layer 1
    hin = p_h1;
    gemm_tc_kernel<128, false><<<gemm_grid, 256>>>(hin, Wp[1], nullptr, nullptr, bp[1], p_m, M);
    agg_kernel<<<agg_grid, 256>>>();
    gemm_tc_kernel<128, true><<<gemm_grid, 256>>>(hin, Ws[1], p_agg, Wn[1], bn[1], p_h2, M);
    // layer 2 (output 64 classes straight into d_out)
    hin = p_h2;
    gemm_tc_kernel<128, false><<<gemm_grid, 256>>>(hin, Wp[2], nullptr, nullptr, bp[2], p_m, M);
    agg_kernel<<<agg_grid, 256>>>();
    gemm_tc_kernel<64, true><<<gemm_grid, 256>>>(hin, Ws[2], p_agg, Wn[2], bn[2], (float*)d_out, M);

    lsm_kernel<<<(M + 7) / 8, 256>>>((float*)d_out, M);
}

// round 3
// speedup vs baseline: 2.1551x; 1.0321x over previous
#include <cuda_runtime.h>
#include <cstdint>

#define N_NODES 100000
#define N_EDGES 800000
#define D 128
#define NCLS 64

// ---------------- scratch (static device globals; no allocation) ------------
__device__ float g_m  [(size_t)N_NODES * D];
__device__ float g_agg[(size_t)N_NODES * D];
__device__ float g_h1 [(size_t)N_NODES * D];
__device__ float g_h2 [(size_t)N_NODES * D];
__device__ int   g_row_start[N_NODES + 1];
__device__ int   g_next[N_NODES];
__device__ int   g_csr [N_EDGES];
// pre-rounded (tf32) weights, packed:
//  Wp0 @0, Wp1 @16384, Wp2 @32768, Ws0 @49152, Ws1 @65536, Ws2 @81920,
//  Wn0 @90112, Wn1 @106496, Wn2 @122880  (end 131072)
__device__ float g_wbuf[131072];

// ---------------- small helpers ---------------------------------------------
__device__ __forceinline__ uint32_t f2tf32(float f) {
    uint32_t r;
    asm volatile("cvt.rna.tf32.f32 %0, %1;" : "=r"(r) : "f"(f));
    return r;
}
__device__ __forceinline__ float round_tf32(float f) {
    return __uint_as_float(f2tf32(f));
}

__device__ __forceinline__ void cp_async16(void* smem, const void* gmem, bool pred) {
    uint32_t s = (uint32_t)__cvta_generic_to_shared(smem);
    int sz = pred ? 16 : 0;
    asm volatile("cp.async.cg.shared.global [%0], [%1], 16, %2;\n" :: "r"(s), "l"(gmem), "r"(sz));
}

__device__ __forceinline__ void mma_tf32(float c[4], const uint32_t a[4], const uint32_t b[2]) {
    asm volatile(
        "mma.sync.aligned.m16n8k8.row.col.f32.tf32.tf32.f32 "
        "{%0,%1,%2,%3}, {%4,%5,%6,%7}, {%8,%9}, {%0,%1,%2,%3};"
        : "+f"(c[0]), "+f"(c[1]), "+f"(c[2]), "+f"(c[3])
        : "r"(a[0]), "r"(a[1]), "r"(a[2]), "r"(a[3]), "r"(b[0]), "r"(b[1]));
}

// ---------------- weight pre-rounding ----------------------------------------
__global__ void round_weights_kernel(
    const float* __restrict__ Wp0, const float* __restrict__ Wp1, const float* __restrict__ Wp2,
    const float* __restrict__ Ws0, const float* __restrict__ Ws1, const float* __restrict__ Ws2,
    const float* __restrict__ Wn0, const float* __restrict__ Wn1, const float* __restrict__ Wn2)
{
    int i = blockIdx.x * blockDim.x + threadIdx.x;
    if (i >= 131072) return;
    const float* src; int off;
    if      (i <  16384) { src = Wp0; off = 0;      }
    else if (i <  32768) { src = Wp1; off = 16384;  }
    else if (i <  49152) { src = Wp2; off = 32768;  }
    else if (i <  65536) { src = Ws0; off = 49152;  }
    else if (i <  81920) { src = Ws1; off = 65536;  }
    else if (i <  90112) { src = Ws2; off = 81920;  }
    else if (i < 106496) { src = Wn0; off = 90112;  }
    else if (i < 122880) { src = Wn1; off = 106496; }
    else                 { src = Wn2; off = 122880; }
    g_wbuf[i] = round_tf32(src[i - off]);
}

// ---------------- CSR build -------------------------------------------------
__global__ void zero_counts_kernel() {
    int i = blockIdx.x * blockDim.x + threadIdx.x;
    if (i < N_NODES) g_next[i] = 0;
}

__global__ void hist_kernel(const int4* __restrict__ dst4) {
    int e = blockIdx.x * blockDim.x + threadIdx.x;
    if (e < N_EDGES / 4) {
        int4 d = __ldg(dst4 + e);
        atomicAdd(&g_next[d.x], 1);
        atomicAdd(&g_next[d.y], 1);
        atomicAdd(&g_next[d.z], 1);
        atomicAdd(&g_next[d.w], 1);
    }
}

// shuffle-based single-block exclusive scan: counts (g_next) -> offsets
__global__ void scan_kernel() {
    __shared__ int wsums[32];
    __shared__ int s_carry;
    int tid = threadIdx.x, lane = tid & 31, wid = tid >> 5;
    if (tid == 0) s_carry = 0;
    __syncthreads();
    for (int base = 0; base < N_NODES; base += 4096) {
        int i0 = base + tid * 4;
        int v[4];
        #pragma unroll
        for (int j = 0; j < 4; j++) v[j] = (i0 + j < N_NODES) ? g_next[i0 + j] : 0;
        int tsum = v[0] + v[1] + v[2] + v[3];
        int incl = tsum;
        #pragma unroll
        for (int off = 1; off < 32; off <<= 1) {
            int n = __shfl_up_sync(0xffffffffu, incl, off);
            if (lane >= off) incl += n;
        }
        if (lane == 31) wsums[wid] = incl;
        __syncthreads();
        if (wid == 0) {
            int w = wsums[lane];
            int wincl = w;
            #pragma unroll
            for (int off = 1; off < 32; off <<= 1) {
                int n = __shfl_up_sync(0xffffffffu, wincl, off);
                if (lane >= off) wincl += n;
            }
            wsums[lane] = wincl - w;   // exclusive warp prefix
        }
        __syncthreads();
        int e = s_carry + wsums[wid] + (incl - tsum);
        #pragma unroll
        for (int j = 0; j < 4; j++) {
            if (i0 + j < N_NODES) { g_row_start[i0 + j] = e; g_next[i0 + j] = e; }
            e += v[j];
        }
        __syncthreads();
        if (tid == 1023) s_carry += wsums[31] + incl;
        __syncthreads();
    }
    if (threadIdx.x == 0) g_row_start[N_NODES] = s_carry;
}

__global__ void fill_kernel(const int4* __restrict__ src4, const int4* __restrict__ dst4) {
    int e = blockIdx.x * blockDim.x + threadIdx.x;
    if (e < N_EDGES / 4) {
        int4 s = __ldg(src4 + e);
        int4 d = __ldg(dst4 + e);
        g_csr[atomicAdd(&g_next[d.x], 1)] = s.x;
        g_csr[atomicAdd(&g_next[d.y], 1)] = s.y;
        g_csr[atomicAdd(&g_next[d.z], 1)] = s.z;
        g_csr[atomicAdd(&g_next[d.w], 1)] = s.w;
    }
}

// ---------------- segment-max aggregation (warp per node) -------------------
// relu output is >= 0, so acc init 0 == segment_max with -inf->0 fixup.
// max of tf32-rounded inputs is tf32-rounded => g_agg needs no cvt downstream.
__global__ void agg_kernel() {
    int warp = (blockIdx.x * blockDim.x + threadIdx.x) >> 5;
    int lane = threadIdx.x & 31;
    if (warp >= N_NODES) return;
    int s = g_row_start[warp];
    int e = g_row_start[warp + 1];
    float4 acc = make_float4(0.f, 0.f, 0.f, 0.f);
    const float4* mp = (const float4*)g_m;
    int i = s;
    for (; i + 4 <= e; i += 4) {
        int s0 = __ldg(&g_csr[i]),     s1 = __ldg(&g_csr[i + 1]);
        int s2 = __ldg(&g_csr[i + 2]), s3 = __ldg(&g_csr[i + 3]);
        float4 v0 = __ldg(mp + (size_t)s0 * 32 + lane);
        float4 v1 = __ldg(mp + (size_t)s1 * 32 + lane);
        float4 v2 = __ldg(mp + (size_t)s2 * 32 + lane);
        float4 v3 = __ldg(mp + (size_t)s3 * 32 + lane);
        acc.x = fmaxf(acc.x, fmaxf(fmaxf(v0.x, v1.x), fmaxf(v2.x, v3.x)));
        acc.y = fmaxf(acc.y, fmaxf(fmaxf(v0.y, v1.y), fmaxf(v2.y, v3.y)));
        acc.z = fmaxf(acc.z, fmaxf(fmaxf(v0.z, v1.z), fmaxf(v2.z, v3.z)));
        acc.w = fmaxf(acc.w, fmaxf(fmaxf(v0.w, v1.w), fmaxf(v2.w, v3.w)));
    }
    for (; i < e; i++) {
        int s0 = __ldg(&g_csr[i]);
        float4 v0 = __ldg(mp + (size_t)s0 * 32 + lane);
        acc.x = fmaxf(acc.x, v0.x);
        acc.y = fmaxf(acc.y, v0.y);
        acc.z = fmaxf(acc.z, v0.z);
        acc.w = fmaxf(acc.w, v0.w);
    }
    *(float4*)(g_agg + (size_t)warp * D + lane * 4) = acc;
}

// ---------------- tf32 tensor-core GEMM -------------------------------------
// C[M,BN] = act(A1@B1 (+ A2@B2) + bias); A row-major [M,128], B row-major [128,BN]
// Weights (B) and A2 are pre-rounded tf32; CVT1 controls cvt of A1 fragments.
// ROUND_OUT: store tf32-rounded. LSM: fused log-softmax epilogue (BN=64 only).
template<int BN, bool DUAL, bool CVT1, bool ROUND_OUT, bool LSM>
__global__ void __launch_bounds__(256)
gemm_tc_kernel(const float* __restrict__ A1, const float* __restrict__ B1,
               const float* __restrict__ A2, const float* __restrict__ B2,
               const float* __restrict__ bias, float* __restrict__ C, int M)
{
    constexpr int AS = 20;          // A smem row stride (words)
    constexpr int BS = BN + 8;      // B smem row stride (words), == 8 mod 32
    constexpr int MT = (BN == 128) ? 2 : 1;   // m16 tiles per warp
    constexpr int WM = MT * 16;               // warp M extent
    __shared__ float As[2][128 * AS];
    __shared__ float Bs[2][16 * BS];

    const int tid = threadIdx.x;
    const int wid = tid >> 5;
    const int lane = tid & 31;
    const int g  = lane >> 2;       // groupID
    const int tg = lane & 3;        // threadID in group
    const int warpM = (BN == 128) ? (wid & 3) : wid;
    const int warpN = (BN == 128) ? (wid >> 2) : 0;
    const int rowBase = blockIdx.x * 128;

    float acc[MT][8][4];
    #pragma unroll
    for (int mt = 0; mt < MT; mt++)
        #pragma unroll
        for (int nt = 0; nt < 8; nt++)
            #pragma unroll
            for (int q = 0; q < 4; q++) acc[mt][nt][q] = 0.f;

    const int totalStages = (DUAL ? 2 : 1) * 8;   // 8 stages of BK=16 per pass

    auto load_stage = [&](int buf, int s) {
        int pass = s >> 3;
        int kk = (s & 7) * 16;
        const float* A = (DUAL && pass) ? A2 : A1;
        const float* B = (DUAL && pass) ? B2 : B1;
        // A tile: 128 x 16
        #pragma unroll
        for (int idx = tid; idx < 512; idx += 256) {
            int r = idx >> 2, c4 = (idx & 3) * 4;
            bool p = (rowBase + r) < M;
            cp_async16(&As[buf][r * AS + c4],
                       A + (size_t)(rowBase + r) * 128 + kk + c4, p);
        }
        // B tile: 16 x BN
        #pragma unroll
        for (int idx = tid; idx < 4 * BN; idx += 256) {
            int r = idx / (BN / 4), c4 = (idx % (BN / 4)) * 4;
            cp_async16(&Bs[buf][r * BS + c4],
                       B + (size_t)(kk + r) * BN + c4, true);
        }
        asm volatile("cp.async.commit_group;\n" ::);
    };

    load_stage(0, 0);

    for (int s = 0; s < totalStages; s++) {
        int buf = s & 1;
        if (s + 1 < totalStages) {
            load_stage(buf ^ 1, s + 1);
            asm volatile("cp.async.wait_group 1;\n" ::);
        } else {
            asm volatile("cp.async.wait_group 0;\n" ::);
        }
        __syncthreads();
        const bool needCvt = CVT1 && ((s >> 3) == 0);

        #pragma unroll
        for (int ks = 0; ks < 2; ks++) {
            uint32_t af[MT][4];
            #pragma unroll
            for (int mt = 0; mt < MT; mt++) {
                int r0 = warpM * WM + mt * 16 + g;
                const float* ap = As[buf];
                float a0 = ap[(r0    ) * AS + ks * 8 + tg    ];
                float a1 = ap[(r0 + 8) * AS + ks * 8 + tg    ];
                float a2 = ap[(r0    ) * AS + ks * 8 + tg + 4];
                float a3 = ap[(r0 + 8) * AS + ks * 8 + tg + 4];
                if (needCvt) {
                    af[mt][0] = f2tf32(a0); af[mt][1] = f2tf32(a1);
                    af[mt][2] = f2tf32(a2); af[mt][3] = f2tf32(a3);
                } else {
                    af[mt][0] = __float_as_uint(a0); af[mt][1] = __float_as_uint(a1);
                    af[mt][2] = __float_as_uint(a2); af[mt][3] = __float_as_uint(a3);
                }
            }
            uint32_t bf[8][2];
            #pragma unroll
            for (int nt = 0; nt < 8; nt++) {
                int c0 = warpN * 64 + nt * 8 + g;
                const float* bp = Bs[buf];
                bf[nt][0] = __float_as_uint(bp[(ks * 8 + tg    ) * BS + c0]);
                bf[nt][1] = __float_as_uint(bp[(ks * 8 + tg + 4) * BS + c0]);
            }
            #pragma unroll
            for (int mt = 0; mt < MT; mt++)
                #pragma unroll
                for (int nt = 0; nt < 8; nt++)
                    mma_tf32(acc[mt][nt], af[mt], bf[nt]);
        }
        __syncthreads();
    }

    if (LSM) {
        // BN==64: each warp holds full 64-class rows split across lane quads.
        float v0[16], v1[16];
        #pragma unroll
        for (int nt = 0; nt < 8; nt++) {
            int c0 = nt * 8 + tg * 2;
            float b0 = __ldg(bias + c0), b1 = __ldg(bias + c0 + 1);
            v0[nt * 2    ] = fmaxf(acc[0][nt][0] + b0, 0.f);
            v0[nt * 2 + 1] = fmaxf(acc[0][nt][1] + b1, 0.f);
            v1[nt * 2    ] = fmaxf(acc[0][nt][2] + b0, 0.f);
            v1[nt * 2 + 1] = fmaxf(acc[0][nt][3] + b1, 0.f);
        }
        float mx0 = v0[0], mx1 = v1[0];
        #pragma unroll
        for (int i = 1; i < 16; i++) { mx0 = fmaxf(mx0, v0[i]); mx1 = fmaxf(mx1, v1[i]); }
        #pragma unroll
        for (int o = 1; o <= 2; o <<= 1) {
            mx0 = fmaxf(mx0, __shfl_xor_sync(0xffffffffu, mx0, o));
            mx1 = fmaxf(mx1, __shfl_xor_sync(0xffffffffu, mx1, o));
        }
        float s0 = 0.f, s1 = 0.f;
        #pragma unroll
        for (int i = 0; i < 16; i++) { s0 += expf(v0[i] - mx0); s1 += expf(v1[i] - mx1); }
        #pragma unroll
        for (int o = 1; o <= 2; o <<= 1) {
            s0 += __shfl_xor_sync(0xffffffffu, s0, o);
            s1 += __shfl_xor_sync(0xffffffffu, s1, o);
        }
        float l0 = mx0 + logf(s0), l1 = mx1 + logf(s1);
        int r0 = rowBase + warpM * 16 + g;
        #pragma unroll
        for (int nt = 0; nt < 8; nt++) {
            int c0 = nt * 8 + tg * 2;
            if (r0 < M) {
                float2 o = make_float2(v0[nt * 2] - l0, v0[nt * 2 + 1] - l0);
                *(float2*)(C + (size_t)r0 * 64 + c0) = o;
            }
            if (r0 + 8 < M) {
                float2 o = make_float2(v1[nt * 2] - l1, v1[nt * 2 + 1] - l1);
                *(float2*)(C + (size_t)(r0 + 8) * 64 + c0) = o;
            }
        }
        return;
    }

    // epilogue: bias + relu (+ tf32 round) + store
    #pragma unroll
    for (int mt = 0; mt < MT; mt++) {
        int r0 = rowBase + warpM * WM + mt * 16 + g;
        #pragma unroll
        for (int nt = 0; nt < 8; nt++) {
            int c0 = warpN * 64 + nt * 8 + tg * 2;
            float bv0 = __ldg(bias + c0);
            float bv1 = __ldg(bias + c0 + 1);
            if (r0 < M) {
                float2 o;
                o.x = fmaxf(acc[mt][nt][0] + bv0, 0.f);
                o.y = fmaxf(acc[mt][nt][1] + bv1, 0.f);
                if (ROUND_OUT) { o.x = round_tf32(o.x); o.y = round_tf32(o.y); }
                *(float2*)(C + (size_t)r0 * BN + c0) = o;
            }
            if (r0 + 8 < M) {
                float2 o;
                o.x = fmaxf(acc[mt][nt][2] + bv0, 0.f);
                o.y = fmaxf(acc[mt][nt][3] + bv1, 0.f);
                if (ROUND_OUT) { o.x = round_tf32(o.x); o.y = round_tf32(o.y); }
                *(float2*)(C + (size_t)(r0 + 8) * BN + c0) = o;
            }
        }
    }
}

// ---------------- launch ----------------------------------------------------
extern "C" void kernel_launch(void* const* d_in, const int* in_sizes, int n_in,
                              void* d_out, int out_size) {
    const float* x    = (const float*)d_in[0];
    const int*   esrc = (const int*)d_in[1];
    const int*   edst = (const int*)d_in[2];
    const float *Wp[3], *bp[3], *Ws[3], *Wn[3], *bn[3];
    for (int l = 0; l < 3; l++) {
        Wp[l] = (const float*)d_in[3 + 5 * l + 0];
        bp[l] = (const float*)d_in[3 + 5 * l + 1];
        Ws[l] = (const float*)d_in[3 + 5 * l + 2];
        Wn[l] = (const float*)d_in[3 + 5 * l + 3];
        bn[l] = (const float*)d_in[3 + 5 * l + 4];
    }
    const int M = N_NODES;

    float *p_h1, *p_h2, *p_m, *p_agg, *p_w;
    cudaGetSymbolAddress((void**)&p_h1,  g_h1);
    cudaGetSymbolAddress((void**)&p_h2,  g_h2);
    cudaGetSymbolAddress((void**)&p_m,   g_m);
    cudaGetSymbolAddress((void**)&p_agg, g_agg);
    cudaGetSymbolAddress((void**)&p_w,   g_wbuf);
    const float* WpR[3] = { p_w +      0, p_w +  16384, p_w +  32768 };
    const float* WsR[3] = { p_w +  49152, p_w +  65536, p_w +  81920 };
    const float* WnR[3] = { p_w +  90112, p_w + 106496, p_w + 122880 };

    // weight pre-round + CSR build
    round_weights_kernel<<<512, 256>>>(Wp[0], Wp[1], Wp[2], Ws[0], Ws[1], Ws[2], Wn[0], Wn[1], Wn[2]);
    zero_counts_kernel<<<(N_NODES + 255) / 256, 256>>>();
    hist_kernel<<<(N_EDGES / 4 + 255) / 256, 256>>>((const int4*)edst);
    scan_kernel<<<1, 1024>>>();
    fill_kernel<<<(N_EDGES / 4 + 255) / 256, 256>>>((const int4*)esrc, (const int4*)edst);

    const int gemm_grid = (M + 127) / 128;
    const int agg_grid  = (N_NODES + 7) / 8;   // 8 warps/block

    // layer 0 (A = raw x -> CVT1)
    gemm_tc_kernel<128, false, true,  true,  false><<<gemm_grid, 256>>>(x, WpR[0], nullptr, nullptr, bp[0], p_m, M);
    agg_kernel<<<agg_grid, 256>>>();
    gemm_tc_kernel<128, true,  true,  true,  false><<<gemm_grid, 256>>>(x, WsR[0], p_agg, WnR[0], bn[0], p_h1, M);
    // layer 1 (h1 pre-rounded)
    gemm_tc_kernel<128, false, false, true,  false><<<gemm_grid, 256>>>(p_h1, WpR[1], nullptr, nullptr, bp[1], p_m, M);
    agg_kernel<<<agg_grid, 256>>>();
    gemm_tc_kernel<128, true,  false, true,  false><<<gemm_grid, 256>>>(p_h1, WsR[1], p_agg, WnR[1], bn[1], p_h2, M);
    // layer 2 (fused log-softmax epilogue writes d_out)
    gemm_tc_kernel<128, false, false, true,  false><<<gemm_grid, 256>>>(p_h2, WpR[2], nullptr, nullptr, bp[2], p_m, M);
    agg_kernel<<<agg_grid, 256>>>();
    gemm_tc_kernel<64,  true,  false, false, true ><<<gemm_grid, 256>>>(p_h2, WsR[2], p_agg, WnR[2], bn[2], (float*)d_out, M);
}

// round 4
// speedup vs baseline: 2.7646x; 1.2828x over previous
#include <cuda_runtime.h>
#include <cuda_fp16.h>
#include <cstdint>

#define N_NODES 100000
#define N_EDGES 800000
#define D 128
#define NCLS 64
#define NBLK 391   // ceil(N_NODES/256)

// ---------------- scratch (static device globals; no allocation) ------------
__device__ __half g_mh [(size_t)N_NODES * D];   // pooled features, fp16
__device__ float  g_agg[(size_t)N_NODES * D];
__device__ float  g_h1 [(size_t)N_NODES * D];
__device__ float  g_h2 [(size_t)N_NODES * D];
__device__ int    g_row_start[N_NODES + 1];
__device__ int    g_next[N_NODES];
__device__ int    g_csr [N_EDGES];
__device__ int    g_partials[512];
// pre-rounded (tf32) weights, packed
__device__ float  g_wbuf[131072];

// ---------------- small helpers ---------------------------------------------
__device__ __forceinline__ uint32_t f2tf32(float f) {
    uint32_t r;
    asm volatile("cvt.rna.tf32.f32 %0, %1;" : "=r"(r) : "f"(f));
    return r;
}
__device__ __forceinline__ float round_tf32(float f) {
    return __uint_as_float(f2tf32(f));
}

__device__ __forceinline__ void cp_async16(void* smem, const void* gmem, bool pred) {
    uint32_t s = (uint32_t)__cvta_generic_to_shared(smem);
    int sz = pred ? 16 : 0;
    asm volatile("cp.async.cg.shared.global [%0], [%1], 16, %2;\n" :: "r"(s), "l"(gmem), "r"(sz));
}

__device__ __forceinline__ void mma_tf32(float c[4], const uint32_t a[4], const uint32_t b[2]) {
    asm volatile(
        "mma.sync.aligned.m16n8k8.row.col.f32.tf32.tf32.f32 "
        "{%0,%1,%2,%3}, {%4,%5,%6,%7}, {%8,%9}, {%0,%1,%2,%3};"
        : "+f"(c[0]), "+f"(c[1]), "+f"(c[2]), "+f"(c[3])
        : "r"(a[0]), "r"(a[1]), "r"(a[2]), "r"(a[3]), "r"(b[0]), "r"(b[1]));
}

// ---------------- weight pre-rounding ----------------------------------------
__global__ void round_weights_kernel(
    const float* __restrict__ Wp0, const float* __restrict__ Wp1, const float* __restrict__ Wp2,
    const float* __restrict__ Ws0, const float* __restrict__ Ws1, const float* __restrict__ Ws2,
    const float* __restrict__ Wn0, const float* __restrict__ Wn1, const float* __restrict__ Wn2)
{
    int i = blockIdx.x * blockDim.x + threadIdx.x;
    if (i >= 131072) return;
    const float* src; int off;
    if      (i <  16384) { src = Wp0; off = 0;      }
    else if (i <  32768) { src = Wp1; off = 16384;  }
    else if (i <  49152) { src = Wp2; off = 32768;  }
    else if (i <  65536) { src = Ws0; off = 49152;  }
    else if (i <  81920) { src = Ws1; off = 65536;  }
    else if (i <  90112) { src = Ws2; off = 81920;  }
    else if (i < 106496) { src = Wn0; off = 90112;  }
    else if (i < 122880) { src = Wn1; off = 106496; }
    else                 { src = Wn2; off = 122880; }
    g_wbuf[i] = round_tf32(src[i - off]);
}

// ---------------- CSR build -------------------------------------------------
__global__ void zero_counts_kernel() {
    int i = blockIdx.x * blockDim.x + threadIdx.x;
    if (i < N_NODES) g_next[i] = 0;
}

__global__ void hist_kernel(const int4* __restrict__ dst4) {
    int e = blockIdx.x * blockDim.x + threadIdx.x;
    if (e < N_EDGES / 4) {
        int4 d = __ldg(dst4 + e);
        atomicAdd(&g_next[d.x], 1);
        atomicAdd(&g_next[d.y], 1);
        atomicAdd(&g_next[d.z], 1);
        atomicAdd(&g_next[d.w], 1);
    }
}

// phase 1: per-block sum of 256 counts
__global__ void reduce_counts_kernel() {
    int i = blockIdx.x * 256 + threadIdx.x;
    int lane = threadIdx.x & 31, wid = threadIdx.x >> 5;
    int v = (i < N_NODES) ? g_next[i] : 0;
    #pragma unroll
    for (int o = 16; o; o >>= 1) v += __shfl_xor_sync(0xffffffffu, v, o);
    __shared__ int ws[8];
    if (lane == 0) ws[wid] = v;
    __syncthreads();
    if (threadIdx.x == 0) {
        int s = 0;
        #pragma unroll
        for (int j = 0; j < 8; j++) s += ws[j];
        g_partials[blockIdx.x] = s;
    }
}

// phase 2: single-block exclusive scan of NBLK partials (NBLK <= 512)
__global__ void scan_partials_kernel() {
    int tid = threadIdx.x, lane = tid & 31, wid = tid >> 5;
    int v = (tid < NBLK) ? g_partials[tid] : 0;
    int incl = v;
    #pragma unroll
    for (int o = 1; o < 32; o <<= 1) {
        int n = __shfl_up_sync(0xffffffffu, incl, o);
        if (lane >= o) incl += n;
    }
    __shared__ int ws[16];
    if (lane == 31) ws[wid] = incl;
    __syncthreads();
    if (wid == 0) {
        int w = (lane < 16) ? ws[lane] : 0;
        int wi = w;
        #pragma unroll
        for (int o = 1; o < 16; o <<= 1) {
            int n = __shfl_up_sync(0xffffffffu, wi, o);
            if (lane >= o) wi += n;
        }
        if (lane < 16) ws[lane] = wi - w;
    }
    __syncthreads();
    int excl = ws[wid] + incl - v;
    if (tid < NBLK) g_partials[tid] = excl;
    if (tid == NBLK) g_row_start[N_NODES] = excl;   // total
}

// phase 3: per-block exclusive scan of counts + block offset -> offsets
__global__ void write_offsets_kernel() {
    int i = blockIdx.x * 256 + threadIdx.x;
    int lane = threadIdx.x & 31, wid = threadIdx.x >> 5;
    int v = (i < N_NODES) ? g_next[i] : 0;
    int incl = v;
    #pragma unroll
    for (int o = 1; o < 32; o <<= 1) {
        int n = __shfl_up_sync(0xffffffffu, incl, o);
        if (lane >= o) incl += n;
    }
    __shared__ int ws[8];
    if (lane == 31) ws[wid] = incl;
    __syncthreads();
    if (wid == 0) {
        int w = (lane < 8) ? ws[lane] : 0;
        int wi = w;
        #pragma unroll
        for (int o = 1; o < 8; o <<= 1) {
            int n = __shfl_up_sync(0xffffffffu, wi, o);
            if (lane >= o) wi += n;
        }
        if (lane < 8) ws[lane] = wi - w;
    }
    __syncthreads();
    int excl = g_partials[blockIdx.x] + ws[wid] + incl - v;
    if (i < N_NODES) { g_row_start[i] = excl; g_next[i] = excl; }
}

__global__ void fill_kernel(const int4* __restrict__ src4, const int4* __restrict__ dst4) {
    int e = blockIdx.x * blockDim.x + threadIdx.x;
    if (e < N_EDGES / 4) {
        int4 s = __ldg(src4 + e);
        int4 d = __ldg(dst4 + e);
        g_csr[atomicAdd(&g_next[d.x], 1)] = s.x;
        g_csr[atomicAdd(&g_next[d.y], 1)] = s.y;
        g_csr[atomicAdd(&g_next[d.z], 1)] = s.z;
        g_csr[atomicAdd(&g_next[d.w], 1)] = s.w;
    }
}

// ---------------- segment-max aggregation (warp per node, fp16 gather) ------
// relu output >= 0 so acc init 0 == segment_max with -inf->0 fixup.
// __hmax2 on fp16-rounded values is exact; fp16 subset of tf32 => no cvt later.
__global__ void agg_kernel() {
    int warp = (blockIdx.x * blockDim.x + threadIdx.x) >> 5;
    int lane = threadIdx.x & 31;
    if (warp >= N_NODES) return;
    int s = g_row_start[warp];
    int e = g_row_start[warp + 1];
    __half2 acc0 = __float2half2_rn(0.f);
    __half2 acc1 = acc0;
    const uint2* mp = (const uint2*)g_mh;   // row stride = 32 uint2 (128 halves)
    int i = s;
    for (; i + 4 <= e; i += 4) {
        int s0 = __ldg(&g_csr[i]),     s1 = __ldg(&g_csr[i + 1]);
        int s2 = __ldg(&g_csr[i + 2]), s3 = __ldg(&g_csr[i + 3]);
        uint2 v0 = __ldg(mp + (size_t)s0 * 32 + lane);
        uint2 v1 = __ldg(mp + (size_t)s1 * 32 + lane);
        uint2 v2 = __ldg(mp + (size_t)s2 * 32 + lane);
        uint2 v3 = __ldg(mp + (size_t)s3 * 32 + lane);
        acc0 = __hmax2(acc0, __hmax2(__hmax2(*(__half2*)&v0.x, *(__half2*)&v1.x),
                                     __hmax2(*(__half2*)&v2.x, *(__half2*)&v3.x)));
        acc1 = __hmax2(acc1, __hmax2(__hmax2(*(__half2*)&v0.y, *(__half2*)&v1.y),
                                     __hmax2(*(__half2*)&v2.y, *(__half2*)&v3.y)));
    }
    for (; i < e; i++) {
        int s0 = __ldg(&g_csr[i]);
        uint2 v0 = __ldg(mp + (size_t)s0 * 32 + lane);
        acc0 = __hmax2(acc0, *(__half2*)&v0.x);
        acc1 = __hmax2(acc1, *(__half2*)&v0.y);
    }
    float2 f0 = __half22float2(acc0);
    float2 f1 = __half22float2(acc1);
    *(float4*)(g_agg + (size_t)warp * D + lane * 4) = make_float4(f0.x, f0.y, f1.x, f1.y);
}

// ---------------- tf32 tensor-core GEMM -------------------------------------
// OM: 0 = fp32 tf32-rounded store, 1 = fp16 store, 2 = fused log-softmax (BN=64)
template<int BN, bool DUAL, bool CVT1, int OM>
__global__ void __launch_bounds__(256)
gemm_tc_kernel(const float* __restrict__ A1, const float* __restrict__ B1,
               const float* __restrict__ A2, const float* __restrict__ B2,
               const float* __restrict__ bias, void* __restrict__ Cv, int M)
{
    constexpr int AS = 20;
    constexpr int BS = BN + 8;
    constexpr int MT = (BN == 128) ? 2 : 1;
    constexpr int WM = MT * 16;
    __shared__ float As[2][128 * AS];
    __shared__ float Bs[2][16 * BS];

    const int tid = threadIdx.x;
    const int wid = tid >> 5;
    const int lane = tid & 31;
    const int g  = lane >> 2;
    const int tg = lane & 3;
    const int warpM = (BN == 128) ? (wid & 3) : wid;
    const int warpN = (BN == 128) ? (wid >> 2) : 0;
    const int rowBase = blockIdx.x * 128;

    float acc[MT][8][4];
    #pragma unroll
    for (int mt = 0; mt < MT; mt++)
        #pragma unroll
        for (int nt = 0; nt < 8; nt++)
            #pragma unroll
            for (int q = 0; q < 4; q++) acc[mt][nt][q] = 0.f;

    const int totalStages = (DUAL ? 2 : 1) * 8;

    auto load_stage = [&](int buf, int s) {
        int pass = s >> 3;
        int kk = (s & 7) * 16;
        const float* A = (DUAL && pass) ? A2 : A1;
        const float* B = (DUAL && pass) ? B2 : B1;
        #pragma unroll
        for (int idx = tid; idx < 512; idx += 256) {
            int r = idx >> 2, c4 = (idx & 3) * 4;
            bool p = (rowBase + r) < M;
            cp_async16(&As[buf][r * AS + c4],
                       A + (size_t)(rowBase + r) * 128 + kk + c4, p);
        }
        #pragma unroll
        for (int idx = tid; idx < 4 * BN; idx += 256) {
            int r = idx / (BN / 4), c4 = (idx % (BN / 4)) * 4;
            cp_async16(&Bs[buf][r * BS + c4],
                       B + (size_t)(kk + r) * BN + c4, true);
        }
        asm volatile("cp.async.commit_group;\n" ::);
    };

    load_stage(0, 0);

    for (int s = 0; s < totalStages; s++) {
        int buf = s & 1;
        if (s + 1 < totalStages) {
            load_stage(buf ^ 1, s + 1);
            asm volatile("cp.async.wait_group 1;\n" ::);
        } else {
            asm volatile("cp.async.wait_group 0;\n" ::);
        }
        __syncthreads();
        const bool needCvt = CVT1 && ((s >> 3) == 0);

        #pragma unroll
        for (int ks = 0; ks < 2; ks++) {
            uint32_t af[MT][4];
            #pragma unroll
            for (int mt = 0; mt < MT; mt++) {
                int r0 = warpM * WM + mt * 16 + g;
                const float* ap = As[buf];
                float a0 = ap[(r0    ) * AS + ks * 8 + tg    ];
                float a1 = ap[(r0 + 8) * AS + ks * 8 + tg    ];
                float a2 = ap[(r0    ) * AS + ks * 8 + tg + 4];
                float a3 = ap[(r0 + 8) * AS + ks * 8 + tg + 4];
                if (needCvt) {
                    af[mt][0] = f2tf32(a0); af[mt][1] = f2tf32(a1);
                    af[mt][2] = f2tf32(a2); af[mt][3] = f2tf32(a3);
                } else {
                    af[mt][0] = __float_as_uint(a0); af[mt][1] = __float_as_uint(a1);
                    af[mt][2] = __float_as_uint(a2); af[mt][3] = __float_as_uint(a3);
                }
            }
            uint32_t bf[8][2];
            #pragma unroll
            for (int nt = 0; nt < 8; nt++) {
                int c0 = warpN * 64 + nt * 8 + g;
                const float* bp = Bs[buf];
                bf[nt][0] = __float_as_uint(bp[(ks * 8 + tg    ) * BS + c0]);
                bf[nt][1] = __float_as_uint(bp[(ks * 8 + tg + 4) * BS + c0]);
            }
            #pragma unroll
            for (int mt = 0; mt < MT; mt++)
                #pragma unroll
                for (int nt = 0; nt < 8; nt++)
                    mma_tf32(acc[mt][nt], af[mt], bf[nt]);
        }
        __syncthreads();
    }

    if (OM == 2) {
        float* C = (float*)Cv;
        float v0[16], v1[16];
        #pragma unroll
        for (int nt = 0; nt < 8; nt++) {
            int c0 = nt * 8 + tg * 2;
            float b0 = __ldg(bias + c0), b1 = __ldg(bias + c0 + 1);
            v0[nt * 2    ] = fmaxf(acc[0][nt][0] + b0, 0.f);
            v0[nt * 2 + 1] = fmaxf(acc[0][nt][1] + b1, 0.f);
            v1[nt * 2    ] = fmaxf(acc[0][nt][2] + b0, 0.f);
            v1[nt * 2 + 1] = fmaxf(acc[0][nt][3] + b1, 0.f);
        }
        float mx0 = v0[0], mx1 = v1[0];
        #pragma unroll
        for (int i = 1; i < 16; i++) { mx0 = fmaxf(mx0, v0[i]); mx1 = fmaxf(mx1, v1[i]); }
        #pragma unroll
        for (int o = 1; o <= 2; o <<= 1) {
            mx0 = fmaxf(mx0, __shfl_xor_sync(0xffffffffu, mx0, o));
            mx1 = fmaxf(mx1, __shfl_xor_sync(0xffffffffu, mx1, o));
        }
        float s0 = 0.f, s1 = 0.f;
        #pragma unroll
        for (int i = 0; i < 16; i++) { s0 += expf(v0[i] - mx0); s1 += expf(v1[i] - mx1); }
        #pragma unroll
        for (int o = 1; o <= 2; o <<= 1) {
            s0 += __shfl_xor_sync(0xffffffffu, s0, o);
            s1 += __shfl_xor_sync(0xffffffffu, s1, o);
        }
        float l0 = mx0 + logf(s0), l1 = mx1 + logf(s1);
        int r0 = rowBase + warpM * 16 + g;
        #pragma unroll
        for (int nt = 0; nt < 8; nt++) {
            int c0 = nt * 8 + tg * 2;
            if (r0 < M)
                *(float2*)(C + (size_t)r0 * 64 + c0) =
                    make_float2(v0[nt * 2] - l0, v0[nt * 2 + 1] - l0);
            if (r0 + 8 < M)
                *(float2*)(C + (size_t)(r0 + 8) * 64 + c0) =
                    make_float2(v1[nt * 2] - l1, v1[nt * 2 + 1] - l1);
        }
        return;
    }

    #pragma unroll
    for (int mt = 0; mt < MT; mt++) {
        int r0 = rowBase + warpM * WM + mt * 16 + g;
        #pragma unroll
        for (int nt = 0; nt < 8; nt++) {
            int c0 = warpN * 64 + nt * 8 + tg * 2;
            float bv0 = __ldg(bias + c0);
            float bv1 = __ldg(bias + c0 + 1);
            float x0 = fmaxf(acc[mt][nt][0] + bv0, 0.f);
            float y0 = fmaxf(acc[mt][nt][1] + bv1, 0.f);
            float x1 = fmaxf(acc[mt][nt][2] + bv0, 0.f);
            float y1 = fmaxf(acc[mt][nt][3] + bv1, 0.f);
            if (OM == 1) {
                __half* C = (__half*)Cv;
                if (r0 < M)     *(__half2*)(C + (size_t)r0 * BN + c0)       = __floats2half2_rn(x0, y0);
                if (r0 + 8 < M) *(__half2*)(C + (size_t)(r0 + 8) * BN + c0) = __floats2half2_rn(x1, y1);
            } else {
                float* C = (float*)Cv;
                if (r0 < M)
                    *(float2*)(C + (size_t)r0 * BN + c0) =
                        make_float2(round_tf32(x0), round_tf32(y0));
                if (r0 + 8 < M)
                    *(float2*)(C + (size_t)(r0 + 8) * BN + c0) =
                        make_float2(round_tf32(x1), round_tf32(y1));
            }
        }
    }
}

// ---------------- launch ----------------------------------------------------
extern "C" void kernel_launch(void* const* d_in, const int* in_sizes, int n_in,
                              void* d_out, int out_size) {
    const float* x    = (const float*)d_in[0];
    const int*   esrc = (const int*)d_in[1];
    const int*   edst = (const int*)d_in[2];
    const float *Wp[3], *bp[3], *Ws[3], *Wn[3], *bn[3];
    for (int l = 0; l < 3; l++) {
        Wp[l] = (const float*)d_in[3 + 5 * l + 0];
        bp[l] = (const float*)d_in[3 + 5 * l + 1];
        Ws[l] = (const float*)d_in[3 + 5 * l + 2];
        Wn[l] = (const float*)d_in[3 + 5 * l + 3];
        bn[l] = (const float*)d_in[3 + 5 * l + 4];
    }
    const int M = N_NODES;

    float *p_h1, *p_h2, *p_agg, *p_w;
    __half* p_mh;
    cudaGetSymbolAddress((void**)&p_h1,  g_h1);
    cudaGetSymbolAddress((void**)&p_h2,  g_h2);
    cudaGetSymbolAddress((void**)&p_mh,  g_mh);
    cudaGetSymbolAddress((void**)&p_agg, g_agg);
    cudaGetSymbolAddress((void**)&p_w,   g_wbuf);
    const float* WpR[3] = { p_w +      0, p_w +  16384, p_w +  32768 };
    const float* WsR[3] = { p_w +  49152, p_w +  65536, p_w +  81920 };
    const float* WnR[3] = { p_w +  90112, p_w + 106496, p_w + 122880 };

    // weight pre-round + CSR build
    round_weights_kernel<<<512, 256>>>(Wp[0], Wp[1], Wp[2], Ws[0], Ws[1], Ws[2], Wn[0], Wn[1], Wn[2]);
    zero_counts_kernel<<<NBLK, 256>>>();
    hist_kernel<<<(N_EDGES / 4 + 255) / 256, 256>>>((const int4*)edst);
    reduce_counts_kernel<<<NBLK, 256>>>();
    scan_partials_kernel<<<1, 512>>>();
    write_offsets_kernel<<<NBLK, 256>>>();
    fill_kernel<<<(N_EDGES / 4 + 255) / 256, 256>>>((const int4*)esrc, (const int4*)edst);

    const int gemm_grid = (M + 127) / 128;
    const int agg_grid  = (N_NODES + 7) / 8;

    // layer 0 (A = raw x -> CVT1)
    gemm_tc_kernel<128, false, true,  1><<<gemm_grid, 256>>>(x, WpR[0], nullptr, nullptr, bp[0], p_mh, M);
    agg_kernel<<<agg_grid, 256>>>();
    gemm_tc_kernel<128, true,  true,  0><<<gemm_grid, 256>>>(x, WsR[0], p_agg, WnR[0], bn[0], p_h1, M);
    // layer 1
    gemm_tc_kernel<128, false, false, 1><<<gemm_grid, 256>>>(p_h1, WpR[1], nullptr, nullptr, bp[1], p_mh, M);
    agg_kernel<<<agg_grid, 256>>>();
    gemm_tc_kernel<128, true,  false, 0><<<gemm_grid, 256>>>(p_h1, WsR[1], p_agg, WnR[1], bn[1], p_h2, M);
    // layer 2 (fused log-softmax writes d_out)
    gemm_tc_kernel<128, false, false, 1><<<gemm_grid, 256>>>(p_h2, WpR[2], nullptr, nullptr, bp[2], p_mh, M);
    agg_kernel<<<agg_grid, 256>>>();
    gemm_tc_kernel<64,  true,  false, 2><<<gemm_grid, 256>>>(p_h2, WsR[2], p_agg, WnR[2], bn[2], d_out, M);
}

// round 6
// speedup vs baseline: 3.6414x; 1.3171x over previous
#include <cuda_runtime.h>
#include <cuda_fp16.h>
#include <cstdint>

#define N_NODES 100000
#define N_EDGES 800000
#define D 128
#define NCLS 64
#define NBLK 391   // ceil(N_NODES/256)

// ---------------- scratch (static device globals; no allocation) ------------
__device__ __half g_xh [(size_t)N_NODES * D];   // fp16 copy of x
__device__ __half g_mh [(size_t)N_NODES * D];   // pooled features
__device__ __half g_aggh[(size_t)N_NODES * D];  // aggregated (max) features
__device__ __half g_h1h[(size_t)N_NODES * D];
__device__ __half g_h2h[(size_t)N_NODES * D];
__device__ int    g_row_start[N_NODES + 1];
__device__ int    g_next[N_NODES];
__device__ int    g_csr [N_EDGES];
__device__ int    g_partials[512];
// transposed fp16 weights, [N][K=128] layout, packed:
//  Wp0 @0, Wp1 @16384, Wp2 @32768, Ws0 @49152, Ws1 @65536, Ws2 @81920,
//  Wn0 @90112, Wn1 @106496, Wn2 @122880  (end 131072)
__device__ __half g_wt[131072];

// ---------------- small helpers ---------------------------------------------
__device__ __forceinline__ uint32_t h2_bits(__half2 h) {
    return *reinterpret_cast<uint32_t*>(&h);
}

__device__ __forceinline__ void cp_async16(void* smem, const void* gmem, bool pred) {
    uint32_t s = (uint32_t)__cvta_generic_to_shared(smem);
    int sz = pred ? 16 : 0;
    asm volatile("cp.async.cg.shared.global [%0], [%1], 16, %2;\n" :: "r"(s), "l"(gmem), "r"(sz));
}

__device__ __forceinline__ void mma_f16(float c[4], const uint32_t a[4], const uint32_t b[2]) {
    asm volatile(
        "mma.sync.aligned.m16n8k16.row.col.f32.f16.f16.f32 "
        "{%0,%1,%2,%3}, {%4,%5,%6,%7}, {%8,%9}, {%0,%1,%2,%3};"
        : "+f"(c[0]), "+f"(c[1]), "+f"(c[2]), "+f"(c[3])
        : "r"(a[0]), "r"(a[1]), "r"(a[2]), "r"(a[3]), "r"(b[0]), "r"(b[1]));
}

// ---------------- prep: weights -> fp16 transposed [N][K] --------------------
__global__ void prep_weights_kernel(
    const float* __restrict__ Wp0, const float* __restrict__ Wp1, const float* __restrict__ Wp2,
    const float* __restrict__ Ws0, const float* __restrict__ Ws1, const float* __restrict__ Ws2,
    const float* __restrict__ Wn0, const float* __restrict__ Wn1, const float* __restrict__ Wn2)
{
    int i = blockIdx.x * blockDim.x + threadIdx.x;
    if (i >= 131072) return;
    const float* src; int off; int N;
    if      (i <  16384) { src = Wp0; off = 0;      N = 128; }
    else if (i <  32768) { src = Wp1; off = 16384;  N = 128; }
    else if (i <  49152) { src = Wp2; off = 32768;  N = 128; }
    else if (i <  65536) { src = Ws0; off = 49152;  N = 128; }
    else if (i <  81920) { src = Ws1; off = 65536;  N = 128; }
    else if (i <  90112) { src = Ws2; off = 81920;  N = 64;  }
    else if (i < 106496) { src = Wn0; off = 90112;  N = 128; }
    else if (i < 122880) { src = Wn1; off = 106496; N = 128; }
    else                 { src = Wn2; off = 122880; N = 64;  }
    int li = i - off;
    int n = li >> 7, k = li & 127;      // output [n][k], K = 128
    g_wt[i] = __float2half(src[k * N + n]);
}

// ---------------- prep: x -> fp16 --------------------------------------------
__global__ void xtohalf_kernel(const float4* __restrict__ x4) {
    int i = blockIdx.x * blockDim.x + threadIdx.x;   // 8 floats per thread
    if (i >= (N_NODES * D) / 8) return;
    float4 a = __ldg(x4 + 2 * i);
    float4 b = __ldg(x4 + 2 * i + 1);
    uint4 o;
    o.x = h2_bits(__floats2half2_rn(a.x, a.y));
    o.y = h2_bits(__floats2half2_rn(a.z, a.w));
    o.z = h2_bits(__floats2half2_rn(b.x, b.y));
    o.w = h2_bits(__floats2half2_rn(b.z, b.w));
    ((uint4*)g_xh)[i] = o;
}

// ---------------- CSR build -------------------------------------------------
__global__ void zero_counts_kernel() {
    int i = blockIdx.x * blockDim.x + threadIdx.x;
    if (i < N_NODES) g_next[i] = 0;
}

__global__ void hist_kernel(const int4* __restrict__ dst4) {
    int e = blockIdx.x * blockDim.x + threadIdx.x;
    if (e < N_EDGES / 4) {
        int4 d = __ldg(dst4 + e);
        atomicAdd(&g_next[d.x], 1);
        atomicAdd(&g_next[d.y], 1);
        atomicAdd(&g_next[d.z], 1);
        atomicAdd(&g_next[d.w], 1);
    }
}

__global__ void reduce_counts_kernel() {
    int i = blockIdx.x * 256 + threadIdx.x;
    int lane = threadIdx.x & 31, wid = threadIdx.x >> 5;
    int v = (i < N_NODES) ? g_next[i] : 0;
    #pragma unroll
    for (int o = 16; o; o >>= 1) v += __shfl_xor_sync(0xffffffffu, v, o);
    __shared__ int ws[8];
    if (lane == 0) ws[wid] = v;
    __syncthreads();
    if (threadIdx.x == 0) {
        int s = 0;
        #pragma unroll
        for (int j = 0; j < 8; j++) s += ws[j];
        g_partials[blockIdx.x] = s;
    }
}

__global__ void scan_partials_kernel() {
    int tid = threadIdx.x, lane = tid & 31, wid = tid >> 5;
    int v = (tid < NBLK) ? g_partials[tid] : 0;
    int incl = v;
    #pragma unroll
    for (int o = 1; o < 32; o <<= 1) {
        int n = __shfl_up_sync(0xffffffffu, incl, o);
        if (lane >= o) incl += n;
    }
    __shared__ int ws[16];
    if (lane == 31) ws[wid] = incl;
    __syncthreads();
    if (wid == 0) {
        int w = (lane < 16) ? ws[lane] : 0;
        int wi = w;
        #pragma unroll
        for (int o = 1; o < 16; o <<= 1) {
            int n = __shfl_up_sync(0xffffffffu, wi, o);
            if (lane >= o) wi += n;
        }
        if (lane < 16) ws[lane] = wi - w;
    }
    __syncthreads();
    int excl = ws[wid] + incl - v;
    if (tid < NBLK) g_partials[tid] = excl;
    if (tid == NBLK) g_row_start[N_NODES] = excl;
}

__global__ void write_offsets_kernel() {
    int i = blockIdx.x * 256 + threadIdx.x;
    int lane = threadIdx.x & 31, wid = threadIdx.x >> 5;
    int v = (i < N_NODES) ? g_next[i] : 0;
    int incl = v;
    #pragma unroll
    for (int o = 1; o < 32; o <<= 1) {
        int n = __shfl_up_sync(0xffffffffu, incl, o);
        if (lane >= o) incl += n;
    }
    __shared__ int ws[8];
    if (lane == 31) ws[wid] = incl;
    __syncthreads();
    if (wid == 0) {
        int w = (lane < 8) ? ws[lane] : 0;
        int wi = w;
        #pragma unroll
        for (int o = 1; o < 8; o <<= 1) {
            int n = __shfl_up_sync(0xffffffffu, wi, o);
            if (lane >= o) wi += n;
        }
        if (lane < 8) ws[lane] = wi - w;
    }
    __syncthreads();
    int excl = g_partials[blockIdx.x] + ws[wid] + incl - v;
    if (i < N_NODES) { g_row_start[i] = excl; g_next[i] = excl; }
}

__global__ void fill_kernel(const int4* __restrict__ src4, const int4* __restrict__ dst4) {
    int e = blockIdx.x * blockDim.x + threadIdx.x;
    if (e < N_EDGES / 4) {
        int4 s = __ldg(src4 + e);
        int4 d = __ldg(dst4 + e);
        g_csr[atomicAdd(&g_next[d.x], 1)] = s.x;
        g_csr[atomicAdd(&g_next[d.y], 1)] = s.y;
        g_csr[atomicAdd(&g_next[d.z], 1)] = s.z;
        g_csr[atomicAdd(&g_next[d.w], 1)] = s.w;
    }
}

// ---------------- segment-max aggregation (warp per node, fp16) --------------
// relu output >= 0 so acc init 0 == segment_max with -inf->0 fixup.
__global__ void agg_kernel() {
    int warp = (blockIdx.x * blockDim.x + threadIdx.x) >> 5;
    int lane = threadIdx.x & 31;
    if (warp >= N_NODES) return;
    int s = g_row_start[warp];
    int e = g_row_start[warp + 1];
    __half2 acc0 = __float2half2_rn(0.f);
    __half2 acc1 = acc0;
    const uint2* mp = (const uint2*)g_mh;   // row stride = 32 uint2 (128 halves)
    int i = s;
    for (; i + 4 <= e; i += 4) {
        int s0 = __ldg(&g_csr[i]),     s1 = __ldg(&g_csr[i + 1]);
        int s2 = __ldg(&g_csr[i + 2]), s3 = __ldg(&g_csr[i + 3]);
        uint2 v0 = __ldg(mp + (size_t)s0 * 32 + lane);
        uint2 v1 = __ldg(mp + (size_t)s1 * 32 + lane);
        uint2 v2 = __ldg(mp + (size_t)s2 * 32 + lane);
        uint2 v3 = __ldg(mp + (size_t)s3 * 32 + lane);
        acc0 = __hmax2(acc0, __hmax2(__hmax2(*(__half2*)&v0.x, *(__half2*)&v1.x),
                                     __hmax2(*(__half2*)&v2.x, *(__half2*)&v3.x)));
        acc1 = __hmax2(acc1, __hmax2(__hmax2(*(__half2*)&v0.y, *(__half2*)&v1.y),
                                     __hmax2(*(__half2*)&v2.y, *(__half2*)&v3.y)));
    }
    for (; i < e; i++) {
        int s0 = __ldg(&g_csr[i]);
        uint2 v0 = __ldg(mp + (size_t)s0 * 32 + lane);
        acc0 = __hmax2(acc0, *(__half2*)&v0.x);
        acc1 = __hmax2(acc1, *(__half2*)&v0.y);
    }
    uint2 o;
    o.x = h2_bits(acc0);
    o.y = h2_bits(acc1);
    ((uint2*)g_aggh)[(size_t)warp * 32 + lane] = o;
}

// ---------------- fp16 tensor-core GEMM --------------------------------------
// C[M,BN] = act(A1@B1t^T (+ A2@B2t^T) + bias)
// A: [M,128] fp16 row-major. Bt: [BN][128] fp16 (transposed weight, k-contig).
// OM: 1 = fp16 store (relu), 2 = fused log-softmax -> fp32 (BN=64 only)
template<int BN, bool DUAL, int OM>
__global__ void __launch_bounds__(256)
gemm_h_kernel(const __half* __restrict__ A1, const __half* __restrict__ B1,
              const __half* __restrict__ A2, const __half* __restrict__ B2,
              const float* __restrict__ bias, void* __restrict__ Cv, int M)
{
    constexpr int ST = 20;                  // smem row stride in 32-bit words
    constexpr int MT = (BN == 128) ? 2 : 1;
    constexpr int WM = MT * 16;
    __shared__ uint32_t As[2][128 * ST];
    __shared__ uint32_t Bs[2][BN * ST];

    const int tid = threadIdx.x;
    const int wid = tid >> 5;
    const int lane = tid & 31;
    const int g  = lane >> 2;
    const int tg = lane & 3;
    const int warpM = (BN == 128) ? (wid & 3) : wid;
    const int warpN = (BN == 128) ? (wid >> 2) : 0;
    const int rowBase = blockIdx.x * 128;

    float acc[MT][8][4];
    #pragma unroll
    for (int mt = 0; mt < MT; mt++)
        #pragma unroll
        for (int nt = 0; nt < 8; nt++)
            #pragma unroll
            for (int q = 0; q < 4; q++) acc[mt][nt][q] = 0.f;

    const int totalStages = (DUAL ? 2 : 1) * 4;   // BK = 32 halves

    auto load_stage = [&](int buf, int s) {
        int pass = s >> 2;
        int kk = (s & 3) * 32;                    // k offset in halves
        const __half* A  = (DUAL && pass) ? A2 : A1;
        const __half* Bt = (DUAL && pass) ? B2 : B1;
        // A tile: 128 rows x 32 halves (4 x 16B chunks per row)
        #pragma unroll
        for (int idx = tid; idx < 512; idx += 256) {
            int r = idx >> 2, c = idx & 3;
            bool p = (rowBase + r) < M;
            cp_async16(&As[buf][r * ST + c * 4],
                       A + (size_t)(rowBase + r) * 128 + kk + c * 8, p);
        }
        // B tile: BN rows x 32 halves
        #pragma unroll
        for (int idx = tid; idx < BN * 4; idx += 256) {
            int n = idx >> 2, c = idx & 3;
            cp_async16(&Bs[buf][n * ST + c * 4],
                       Bt + (size_t)n * 128 + kk + c * 8, true);
        }
        asm volatile("cp.async.commit_group;\n" ::);
    };

    load_stage(0, 0);

    for (int s = 0; s < totalStages; s++) {
        int buf = s & 1;
        if (s + 1 < totalStages) {
            load_stage(buf ^ 1, s + 1);
            asm volatile("cp.async.wait_group 1;\n" ::);
        } else {
            asm volatile("cp.async.wait_group 0;\n" ::);
        }
        __syncthreads();

        #pragma unroll
        for (int ks = 0; ks < 2; ks++) {          // two k16 steps per BK=32
            uint32_t af[MT][4];
            #pragma unroll
            for (int mt = 0; mt < MT; mt++) {
                int r0 = warpM * WM + mt * 16 + g;
                const uint32_t* ap = As[buf];
                af[mt][0] = ap[(r0    ) * ST + ks * 8 + tg    ];
                af[mt][1] = ap[(r0 + 8) * ST + ks * 8 + tg    ];
                af[mt][2] = ap[(r0    ) * ST + ks * 8 + tg + 4];
                af[mt][3] = ap[(r0 + 8) * ST + ks * 8 + tg + 4];
            }
            uint32_t bf[8][2];
            #pragma unroll
            for (int nt = 0; nt < 8; nt++) {
                int c0 = warpN * 64 + nt * 8 + g;
                const uint32_t* bp = Bs[buf];
                bf[nt][0] = bp[c0 * ST + ks * 8 + tg    ];
                bf[nt][1] = bp[c0 * ST + ks * 8 + tg + 4];
            }
            #pragma unroll
            for (int mt = 0; mt < MT; mt++)
                #pragma unroll
                for (int nt = 0; nt < 8; nt++)
                    mma_f16(acc[mt][nt], af[mt], bf[nt]);
        }
        __syncthreads();
    }

    if (OM == 2) {
        float* C = (float*)Cv;
        float v0[16], v1[16];
        #pragma unroll
        for (int nt = 0; nt < 8; nt++) {
            int c0 = nt * 8 + tg * 2;
            float b0 = __ldg(bias + c0), b1 = __ldg(bias + c0 + 1);
            v0[nt * 2    ] = fmaxf(acc[0][nt][0] + b0, 0.f);
            v0[nt * 2 + 1] = fmaxf(acc[0][nt][1] + b1, 0.f);
            v1[nt * 2    ] = fmaxf(acc[0][nt][2] + b0, 0.f);
            v1[nt * 2 + 1] = fmaxf(acc[0][nt][3] + b1, 0.f);
        }
        float mx0 = v0[0], mx1 = v1[0];
        #pragma unroll
        for (int i = 1; i < 16; i++) { mx0 = fmaxf(mx0, v0[i]); mx1 = fmaxf(mx1, v1[i]); }
        #pragma unroll
        for (int o = 1; o <= 2; o <<= 1) {
            mx0 = fmaxf(mx0, __shfl_xor_sync(0xffffffffu, mx0, o));
            mx1 = fmaxf(mx1, __shfl_xor_sync(0xffffffffu, mx1, o));
        }
        float s0 = 0.f, s1 = 0.f;
        #pragma unroll
        for (int i = 0; i < 16; i++) { s0 += expf(v0[i] - mx0); s1 += expf(v1[i] - mx1); }
        #pragma unroll
        for (int o = 1; o <= 2; o <<= 1) {
            s0 += __shfl_xor_sync(0xffffffffu, s0, o);
            s1 += __shfl_xor_sync(0xffffffffu, s1, o);
        }
        float l0 = mx0 + logf(s0), l1 = mx1 + logf(s1);
        int r0 = rowBase + warpM * 16 + g;
        #pragma unroll
        for (int nt = 0; nt < 8; nt++) {
            int c0 = nt * 8 + tg * 2;
            if (r0 < M)
                *(float2*)(C + (size_t)r0 * 64 + c0) =
                    make_float2(v0[nt * 2] - l0, v0[nt * 2 + 1] - l0);
            if (r0 + 8 < M)
                *(float2*)(C + (size_t)(r0 + 8) * 64 + c0) =
                    make_float2(v1[nt * 2] - l1, v1[nt * 2 + 1] - l1);
        }
        return;
    }

    // OM == 1: bias + relu -> fp16
    __half* C = (__half*)Cv;
    #pragma unroll
    for (int mt = 0; mt < MT; mt++) {
        int r0 = rowBase + warpM * WM + mt * 16 + g;
        #pragma unroll
        for (int nt = 0; nt < 8; nt++) {
            int c0 = warpN * 64 + nt * 8 + tg * 2;
            float bv0 = __ldg(bias + c0);
            float bv1 = __ldg(bias + c0 + 1);
            if (r0 < M) {
                *(__half2*)(C + (size_t)r0 * BN + c0) =
                    __floats2half2_rn(fmaxf(acc[mt][nt][0] + bv0, 0.f),
                                      fmaxf(acc[mt][nt][1] + bv1, 0.f));
            }
            if (r0 + 8 < M) {
                *(__half2*)(C + (size_t)(r0 + 8) * BN + c0) =
                    __floats2half2_rn(fmaxf(acc[mt][nt][2] + bv0, 0.f),
                                      fmaxf(acc[mt][nt][3] + bv1, 0.f));
            }
        }
    }
}

// ---------------- launch ----------------------------------------------------
extern "C" void kernel_launch(void* const* d_in, const int* in_sizes, int n_in,
                              void* d_out, int out_size) {
    const float* x    = (const float*)d_in[0];
    const int*   esrc = (const int*)d_in[1];
    const int*   edst = (const int*)d_in[2];
    const float *Wp[3], *bp[3], *Ws[3], *Wn[3], *bn[3];
    for (int l = 0; l < 3; l++) {
        Wp[l] = (const float*)d_in[3 + 5 * l + 0];
        bp[l] = (const float*)d_in[3 + 5 * l + 1];
        Ws[l] = (const float*)d_in[3 + 5 * l + 2];
        Wn[l] = (const float*)d_in[3 + 5 * l + 3];
        bn[l] = (const float*)d_in[3 + 5 * l + 4];
    }
    const int M = N_NODES;

    __half *p_xh, *p_mh, *p_aggh, *p_h1h, *p_h2h, *p_w;
    cudaGetSymbolAddress((void**)&p_xh,   g_xh);
    cudaGetSymbolAddress((void**)&p_mh,   g_mh);
    cudaGetSymbolAddress((void**)&p_aggh, g_aggh);
    cudaGetSymbolAddress((void**)&p_h1h,  g_h1h);
    cudaGetSymbolAddress((void**)&p_h2h,  g_h2h);
    cudaGetSymbolAddress((void**)&p_w,    g_wt);
    const __half* WpT[3] = { p_w +      0, p_w +  16384, p_w +  32768 };
    const __half* WsT[3] = { p_w +  49152, p_w +  65536, p_w +  81920 };
    const __half* WnT[3] = { p_w +  90112, p_w + 106496, p_w + 122880 };

    // prep + CSR build
    prep_weights_kernel<<<512, 256>>>(Wp[0], Wp[1], Wp[2], Ws[0], Ws[1], Ws[2], Wn[0], Wn[1], Wn[2]);
    xtohalf_kernel<<<(N_NODES * D / 8 + 255) / 256, 256>>>((const float4*)x);
    zero_counts_kernel<<<NBLK, 256>>>();
    hist_kernel<<<(N_EDGES / 4 + 255) / 256, 256>>>((const int4*)edst);
    reduce_counts_kernel<<<NBLK, 256>>>();
    scan_partials_kernel<<<1, 512>>>();
    write_offsets_kernel<<<NBLK, 256>>>();
    fill_kernel<<<(N_EDGES / 4 + 255) / 256, 256>>>((const int4*)esrc, (const int4*)edst);

    const int gemm_grid = (M + 127) / 128;
    const int agg_grid  = (N_NODES + 7) / 8;

    // layer 0
    gemm_h_kernel<128, false, 1><<<gemm_grid, 256>>>(p_xh, WpT[0], nullptr, nullptr, bp[0], p_mh, M);
    agg_kernel<<<agg_grid, 256>>>();
    gemm_h_kernel<128, true,  1><<<gemm_grid, 256>>>(p_xh, WsT[0], p_aggh, WnT[0], bn[0], p_h1h, M);
    // layer 1
    gemm_h_kernel<128, false, 1><<<gemm_grid, 256>>>(p_h1h, WpT[1], nullptr, nullptr, bp[1], p_mh, M);
    agg_kernel<<<agg_grid, 256>>>();
    gemm_h_kernel<128, true,  1><<<gemm_grid, 256>>>(p_h1h, WsT[1], p_aggh, WnT[1], bn[1], p_h2h, M);
    // layer 2 (fused log-softmax writes d_out)
    gemm_h_kernel<128, false, 1><<<gemm_grid, 256>>>(p_h2h, WpT[2], nullptr, nullptr, bp[2], p_mh, M);
    agg_kernel<<<agg_grid, 256>>>();
    gemm_h_kernel<64,  true,  2><<<gemm_grid, 256>>>(p_h2h, WsT[2], p_aggh, WnT[2], bn[2], d_out, M);
}